// round 11
// baseline (speedup 1.0000x reference)
#include <cuda_runtime.h>
#include <cuda_bf16.h>

#define NUM_P 196          // 14*14 patch locations

// ---------------------------------------------------------------------------
// Thread-local gate helpers on 8 amplitudes.
// Local index k bits: 4 = wire1, 2 = wire2, 1 = wire3.  wire0 = lane&1.
// ---------------------------------------------------------------------------
template <int M>
__device__ __forceinline__ void ryR_local(float* a, float cg, float sg) {
#pragma unroll
    for (int k = 0; k < 8; k++)
        if (!(k & M)) {
            const int j = k | M;
            float a0 = a[k], a1 = a[j];
            a[k] = cg * a0 - sg * a1;
            a[j] = sg * a0 + cg * a1;
        }
}

template <int M>
__device__ __forceinline__ void ryC_local(float* ar, float* ai, float cg, float sg) {
#pragma unroll
    for (int k = 0; k < 8; k++)
        if (!(k & M)) {
            const int j = k | M;
            float r0 = ar[k], r1 = ar[j];
            ar[k] = cg * r0 - sg * r1;
            ar[j] = sg * r0 + cg * r1;
            float i0 = ai[k], i1 = ai[j];
            ai[k] = cg * i0 - sg * i1;
            ai[j] = sg * i0 + cg * i1;
        }
}

__device__ __forceinline__ void swapf(float& a, float& b) { float t = a; a = b; b = t; }

// ---------------------------------------------------------------------------
// Pair-split kernel: 784 blocks x 256 threads; block = (patch p, quarter).
// Two threads per circuit (lane parity = wire0 bit); 128 circuits per block.
// ---------------------------------------------------------------------------
__global__ void __launch_bounds__(256, 4)
qf_pair_kernel(const float* __restrict__ x,
               const float* __restrict__ params,
               float* __restrict__ out) {
    __shared__ float sh_s[8], sh_q[8];
    __shared__ float sP0[4];              // params[0][w][0] (merged into input RY)
    __shared__ float sC[3][4], sS[3][4];  // cos/sin: col0=l0c1, col1=l1c0, col2=l1c1
    __shared__ float sPr[16], sPi[16];    // layer-0 RZ phasors (global idx: 8=w0,4=w1,2=w2,1=w3)

    const int p = blockIdx.x >> 2;
    const int quarter = blockIdx.x & 3;
    const int r = p / 14, c = p % 14;
    const int tid = threadIdx.x;
    const int lane = tid & 31, wid = tid >> 5;
    const int side = lane & 1;            // this thread's wire0 bit
    const int b = quarter * 128 + (tid >> 1);   // this pair's sample

    const int poff = (2 * r) * 28 + 2 * c;

    // --- loads: 2 stats samples (tid, tid+256) + this pair's circuit sample ---
    const float* xs0 = x + tid * 784 + poff;
    const float* xs1 = xs0 + 256 * 784;
    const float* xc  = x + b * 784 + poff;
    float s0a = xs0[0], s0b = xs0[1], s0c = xs0[28], s0d = xs0[29];
    float s1a = xs1[0], s1b = xs1[1], s1c = xs1[28], s1d = xs1[29];
    float v0 = xc[0], v1 = xc[1], v2 = xc[28], v3 = xc[29];

    // --- Phase A: stats over all 512 samples (2048 values) ---
    float s = ((s0a + s0b) + (s0c + s0d)) + ((s1a + s1b) + (s1c + s1d));
    float q = (s0a * s0a + s0b * s0b + s0c * s0c + s0d * s0d)
            + (s1a * s1a + s1b * s1b + s1c * s1c + s1d * s1d);
#pragma unroll
    for (int o = 16; o > 0; o >>= 1) {
        s += __shfl_down_sync(0xffffffffu, s, o);
        q += __shfl_down_sync(0xffffffffu, q, o);
    }
    if (lane == 0) { sh_s[wid] = s; sh_q[wid] = q; }

    // --- params precompute, parallel across warp 0 lanes ---
    if (wid == 0) {
        if (lane < 16) {              // one RZ phasor per lane
            float prr = 1.f, pii = 0.f;
#pragma unroll
            for (int w = 0; w < 4; w++) {
                float szv, czv;
                __sincosf(0.5f * params[w * 3 + 2], &szv, &czv);
                float sw_ = (lane & (8 >> w)) ? szv : -szv;
                float nr = prr * czv - pii * sw_;
                pii = prr * sw_ + pii * czv;
                prr = nr;
            }
            sPr[lane] = prr; sPi[lane] = pii;
        } else if (lane < 28) {       // 12 RY gate constants
            int j = lane - 16;
            int col = j >> 2, wire = j & 3;
            int pidx = (col == 0) ? wire * 3 + 1
                     : (col == 1) ? 12 + wire * 3
                                  : 12 + wire * 3 + 1;
            float s_, c_;
            __sincosf(0.5f * params[pidx], &s_, &c_);
            sC[col][wire] = c_; sS[col][wire] = s_;
        } else {                      // merged first RY column angles
            int wire = lane - 28;
            sP0[wire] = params[wire * 3 + 0];
        }
    }
    __syncthreads();

    // redundant final reduce (LDS broadcast; no second barrier)
    float fs = 0.f, fq = 0.f;
#pragma unroll
    for (int i = 0; i < 8; i++) { fs += sh_s[i]; fq += sh_q[i]; }
    const float n = 2048.0f;
    float mean = fs / n;
    float var = fmaxf((fq - fs * mean) / (n - 1.0f), 0.0f);
    float inv = 3.14159265358979323846f / (sqrtf(var) + 1e-8f);

    // --- Phase B: circuit (this thread owns the 8 amps with wire0 = side) ---
    float cw[4], sw[4];
    __sincosf(0.5f * ((v0 - mean) * inv + sP0[0]), &sw[0], &cw[0]);
    __sincosf(0.5f * ((v1 - mean) * inv + sP0[1]), &sw[1], &cw[1]);
    __sincosf(0.5f * ((v2 - mean) * inv + sP0[2]), &sw[2], &cw[2]);
    __sincosf(0.5f * ((v3 - mean) * inv + sP0[3]), &sw[3], &cw[3]);

    // initial product state (real); merged input+l0col0 RYs already in angles
    float a[8];
    {
        float g0 = side ? sw[0] : cw[0];
        float t0 = g0 * cw[1], t1 = g0 * sw[1];
        float u0 = t0 * cw[2], u1 = t0 * sw[2], u2 = t1 * cw[2], u3 = t1 * sw[2];
        a[0] = u0 * cw[3]; a[1] = u0 * sw[3];
        a[2] = u1 * cw[3]; a[3] = u1 * sw[3];
        a[4] = u2 * cw[3]; a[5] = u2 * sw[3];
        a[6] = u3 * cw[3]; a[7] = u3 * sw[3];
    }

    // ---- layer 0 (real) ----
    // cnot(0->1): on odd lanes flip wire1 bit (lane-conditional swap, FSEL)
#pragma unroll
    for (int k = 0; k < 4; k++) {
        float lo = a[k], hi = a[k + 4];
        a[k]     = side ? hi : lo;
        a[k + 4] = side ? lo : hi;
    }
    // cnot(1->2): (4<->6),(5<->7)
    swapf(a[4], a[6]); swapf(a[5], a[7]);
    // cnot(2->3): (2<->3),(6<->7)
    swapf(a[2], a[3]); swapf(a[6], a[7]);

    // RY col1: wire0 via shfl
    {
        float cg = sC[0][0], sv = sS[0][0];
        float sg = side ? sv : -sv;
        float pr[8];
#pragma unroll
        for (int k = 0; k < 8; k++) pr[k] = __shfl_xor_sync(0xffffffffu, a[k], 1);
#pragma unroll
        for (int k = 0; k < 8; k++) a[k] = cg * a[k] + sg * pr[k];
    }
    ryR_local<4>(a, sC[0][1], sS[0][1]);   // wire1
    ryR_local<2>(a, sC[0][2], sS[0][2]);   // wire2
    ryR_local<1>(a, sC[0][3], sS[0][3]);   // wire3

    // cnot(1->0): exchange across pair for k with wire1 bit
#pragma unroll
    for (int k = 4; k < 8; k++) a[k] = __shfl_xor_sync(0xffffffffu, a[k], 1);
    // cnot(2->1): (2<->6),(3<->7)
    swapf(a[2], a[6]); swapf(a[3], a[7]);
    // cnot(3->2): (1<->3),(5<->7)
    swapf(a[1], a[3]); swapf(a[5], a[7]);

    // ---- layer-0 RZ: real -> complex via phasors (global idx = side*8 + k) ----
    float ar[8], ai[8];
    {
        const int base = side << 3;
#pragma unroll
        for (int k = 0; k < 8; k++) {
            ar[k] = a[k] * sPr[base + k];
            ai[k] = a[k] * sPi[base + k];
        }
    }

    // ---- layer 1 (complex; final RZ is pure phase -> skipped) ----
    // RY col0: wire0 via shfl
    {
        float cg = sC[1][0], sv = sS[1][0];
        float sg = side ? sv : -sv;
        float pr[8], pi[8];
#pragma unroll
        for (int k = 0; k < 8; k++) {
            pr[k] = __shfl_xor_sync(0xffffffffu, ar[k], 1);
            pi[k] = __shfl_xor_sync(0xffffffffu, ai[k], 1);
        }
#pragma unroll
        for (int k = 0; k < 8; k++) {
            ar[k] = cg * ar[k] + sg * pr[k];
            ai[k] = cg * ai[k] + sg * pi[k];
        }
    }
    ryC_local<4>(ar, ai, sC[1][1], sS[1][1]);
    ryC_local<2>(ar, ai, sC[1][2], sS[1][2]);
    ryC_local<1>(ar, ai, sC[1][3], sS[1][3]);

    // cnot(0->1): lane-conditional swap on both components
#pragma unroll
    for (int k = 0; k < 4; k++) {
        float lo = ar[k], hi = ar[k + 4];
        ar[k]     = side ? hi : lo;
        ar[k + 4] = side ? lo : hi;
        float li = ai[k], hi2 = ai[k + 4];
        ai[k]     = side ? hi2 : li;
        ai[k + 4] = side ? li : hi2;
    }
    // cnot(1->2), cnot(2->3): renames
    swapf(ar[4], ar[6]); swapf(ar[5], ar[7]); swapf(ai[4], ai[6]); swapf(ai[5], ai[7]);
    swapf(ar[2], ar[3]); swapf(ar[6], ar[7]); swapf(ai[2], ai[3]); swapf(ai[6], ai[7]);

    // RY col1: wire0 via shfl
    {
        float cg = sC[2][0], sv = sS[2][0];
        float sg = side ? sv : -sv;
        float pr[8], pi[8];
#pragma unroll
        for (int k = 0; k < 8; k++) {
            pr[k] = __shfl_xor_sync(0xffffffffu, ar[k], 1);
            pi[k] = __shfl_xor_sync(0xffffffffu, ai[k], 1);
        }
#pragma unroll
        for (int k = 0; k < 8; k++) {
            ar[k] = cg * ar[k] + sg * pr[k];
            ai[k] = cg * ai[k] + sg * pi[k];
        }
    }
    ryC_local<4>(ar, ai, sC[2][1], sS[2][1]);
    ryC_local<2>(ar, ai, sC[2][2], sS[2][2]);
    ryC_local<1>(ar, ai, sC[2][3], sS[2][3]);

    // cnot(1->0): exchange; cnot(2->1), cnot(3->2): renames (probs are
    // permutation-invariant but keep them for exact index mapping — free)
#pragma unroll
    for (int k = 4; k < 8; k++) {
        ar[k] = __shfl_xor_sync(0xffffffffu, ar[k], 1);
        ai[k] = __shfl_xor_sync(0xffffffffu, ai[k], 1);
    }
    swapf(ar[2], ar[6]); swapf(ar[3], ar[7]); swapf(ai[2], ai[6]); swapf(ai[3], ai[7]);
    swapf(ar[1], ar[3]); swapf(ar[5], ar[7]); swapf(ai[1], ai[3]); swapf(ai[5], ai[7]);

    // ---- probabilities ----
    float pv[8];
#pragma unroll
    for (int k = 0; k < 8; k++)
        pv[k] = fmaf(ar[k], ar[k], ai[k] * ai[k]);

    // ---- local Walsh-Hadamard partials (k bits: 4=w1, 2=w2, 1=w3) ----
    float e0 = pv[0] + pv[1], d0 = pv[0] - pv[1];
    float e1 = pv[2] + pv[3], d1 = pv[2] - pv[3];
    float e2 = pv[4] + pv[5], d2 = pv[4] - pv[5];
    float e3 = pv[6] + pv[7], d3 = pv[6] - pv[7];
    float z3p = (d0 + d1) + (d2 + d3);
    float z2p = (e0 - e1) + (e2 - e3);
    float z1p = (e0 + e1) - (e2 + e3);
    float ssum = (e0 + e1) + (e2 + e3);

    // combine across the pair
    float ps  = __shfl_xor_sync(0xffffffffu, ssum, 1);
    float pz1 = __shfl_xor_sync(0xffffffffu, z1p, 1);
    float pz2 = __shfl_xor_sync(0xffffffffu, z2p, 1);
    float pz3 = __shfl_xor_sync(0xffffffffu, z3p, 1);

    if (!side) {
        float4 zo = make_float4(ssum - ps, z1p + pz1, z2p + pz2, z3p + pz3);
        *reinterpret_cast<float4*>(out + b * 784 + p * 4) = zo;
    }
}

// ---------------------------------------------------------------------------
extern "C" void kernel_launch(void* const* d_in, const int* in_sizes, int n_in,
                              void* d_out, int out_size) {
    const float* x = (const float*)d_in[0];
    const float* params = (const float*)d_in[1];
    if (n_in >= 2 && in_sizes[0] == 24) {   // robustness vs input ordering
        x = (const float*)d_in[1];
        params = (const float*)d_in[0];
    }
    float* out = (float*)d_out;

    qf_pair_kernel<<<4 * NUM_P, 256>>>(x, params, out);
}

// round 12
// speedup vs baseline: 1.4090x; 1.4090x over previous
#include <cuda_runtime.h>
#include <cuda_bf16.h>

#define NUM_P 196          // 14*14 patch locations

// ---------------------------------------------------------------------------
// Scalar gate helpers (16 amplitudes in registers, fully unrolled).
// amplitude index bits: 8=wire0, 4=wire1, 2=wire2, 1=wire3
// ---------------------------------------------------------------------------
template <int M>
__device__ __forceinline__ void ry_real(float* a, float c, float s) {
#pragma unroll
    for (int i = 0; i < 16; i++)
        if (!(i & M)) {
            const int j = i | M;
            float a0 = a[i], a1 = a[j];
            a[i] = c * a0 - s * a1;
            a[j] = s * a0 + c * a1;
        }
}

template <int M>
__device__ __forceinline__ void ry_cplx(float* ar, float* ai, float c, float s) {
#pragma unroll
    for (int i = 0; i < 16; i++)
        if (!(i & M)) {
            const int j = i | M;
            float r0 = ar[i], r1 = ar[j];
            ar[i] = c * r0 - s * r1;
            ar[j] = s * r0 + c * r1;
            float i0 = ai[i], i1 = ai[j];
            ai[i] = c * i0 - s * i1;
            ai[j] = s * i0 + c * i1;
        }
}

template <int MC, int MT>
__device__ __forceinline__ void cnot_real(float* a) {
#pragma unroll
    for (int i = 0; i < 16; i++)
        if ((i & MC) && !(i & MT)) {
            const int j = i | MT;
            float t = a[i]; a[i] = a[j]; a[j] = t;   // register rename, free
        }
}

template <int MC, int MT>
__device__ __forceinline__ void cnot_cplx(float* ar, float* ai) {
    cnot_real<MC, MT>(ar);
    cnot_real<MC, MT>(ai);
}

// ---------------------------------------------------------------------------
// Fused kernel: 392 blocks x 256 threads. block = (patch p, batch half).
// Phase A: redundant per-block stats over all 512 samples (single barrier).
// Phase B: one circuit per thread (sample = half*256 + tid).
// ---------------------------------------------------------------------------
__global__ void __launch_bounds__(256)
qf_fused_kernel(const float* __restrict__ x,
                const float* __restrict__ params,
                float* __restrict__ out) {
    __shared__ float sh_s[8], sh_q[8];
    __shared__ float sP0[4];              // params[0][w][0] (merged into input RY)
    __shared__ float2 sCS[12];            // {cos,sin}: [col*4+wire], col: l0c1,l1c0,l1c1
    __shared__ float2 sPh[16];            // layer-0 RZ phasors {pr, pi}

    const int p    = blockIdx.x >> 1;
    const int half = blockIdx.x & 1;
    const int r = p / 14, c = p % 14;
    const int tid = threadIdx.x;
    const int lane = tid & 31, wid = tid >> 5;

    // --- load two samples' 2x2 patches (rows tid and tid+256) ---
    const float* x0 = x + tid * 784 + (2 * r) * 28 + 2 * c;
    const float* x1 = x0 + 256 * 784;
    float w0 = x0[0], w1 = x0[1], w2 = x0[28], w3 = x0[29];
    float y0 = x1[0], y1 = x1[1], y2 = x1[28], y3 = x1[29];

    // --- Phase A: stats over all 512 samples (2048 values) ---
    float s = ((w0 + w1) + (w2 + w3)) + ((y0 + y1) + (y2 + y3));
    float q = (w0 * w0 + w1 * w1 + w2 * w2 + w3 * w3)
            + (y0 * y0 + y1 * y1 + y2 * y2 + y3 * y3);
#pragma unroll
    for (int o = 16; o > 0; o >>= 1) {
        s += __shfl_down_sync(0xffffffffu, s, o);
        q += __shfl_down_sync(0xffffffffu, q, o);
    }
    if (lane == 0) { sh_s[wid] = s; sh_q[wid] = q; }

    // --- params precompute, parallel across warp 1 lanes ---
    if (wid == 1) {
        if (lane < 16) {              // one RZ phasor per lane
            float prr = 1.f, pii = 0.f;
#pragma unroll
            for (int w = 0; w < 4; w++) {
                float szv, czv;
                __sincosf(0.5f * params[w * 3 + 2], &szv, &czv);
                float sw_ = (lane & (8 >> w)) ? szv : -szv;
                float nr = prr * czv - pii * sw_;
                pii = prr * sw_ + pii * czv;
                prr = nr;
            }
            sPh[lane] = make_float2(prr, pii);
        } else if (lane < 28) {       // 12 RY gate constants
            int j = lane - 16;
            int col = j >> 2, wire = j & 3;
            int pidx = (col == 0) ? wire * 3 + 1
                     : (col == 1) ? 12 + wire * 3
                                  : 12 + wire * 3 + 1;
            float s_, c_;
            __sincosf(0.5f * params[pidx], &s_, &c_);
            sCS[j] = make_float2(c_, s_);
        } else {                      // merged first RY column angles
            int wire = lane - 28;
            sP0[wire] = params[wire * 3 + 0];
        }
    }
    __syncthreads();

    // redundant final reduce (LDS broadcast; no second barrier)
    float fs = 0.f, fq = 0.f;
#pragma unroll
    for (int i = 0; i < 8; i++) { fs += sh_s[i]; fq += sh_q[i]; }
    const float n = 2048.0f;
    const float mean = fs / n;
    const float var = fmaxf((fq - fs * mean) / (n - 1.0f), 0.0f);
    const float inv = 3.14159265358979323846f / (sqrtf(var) + 1e-8f);

    // --- Phase B: circuit ---
    float v0 = half ? y0 : w0, v1 = half ? y1 : w1;
    float v2 = half ? y2 : w2, v3 = half ? y3 : w3;

    // input RY merged with layer-0 first RY column
    float cw[4], sw[4];
    __sincosf(0.5f * ((v0 - mean) * inv + sP0[0]), &sw[0], &cw[0]);
    __sincosf(0.5f * ((v1 - mean) * inv + sP0[1]), &sw[1], &cw[1]);
    __sincosf(0.5f * ((v2 - mean) * inv + sP0[2]), &sw[2], &cw[2]);
    __sincosf(0.5f * ((v3 - mean) * inv + sP0[3]), &sw[3], &cw[3]);

    // product state (real)
    float ar[16], ai[16];
    {
        float f01[4] = { cw[0] * cw[1], cw[0] * sw[1], sw[0] * cw[1], sw[0] * sw[1] };
        float f23[4] = { cw[2] * cw[3], cw[2] * sw[3], sw[2] * cw[3], sw[2] * sw[3] };
#pragma unroll
        for (int hi = 0; hi < 4; hi++)
#pragma unroll
            for (int lo = 0; lo < 4; lo++)
                ar[hi * 4 + lo] = f01[hi] * f23[lo];
    }

    // ---- layer 0 remainder (real) ----
    cnot_real<8, 4>(ar); cnot_real<4, 2>(ar); cnot_real<2, 1>(ar);
    {
        float2 g0 = sCS[0], g1 = sCS[1], g2 = sCS[2], g3 = sCS[3];
        ry_real<8>(ar, g0.x, g0.y);
        ry_real<4>(ar, g1.x, g1.y);
        ry_real<2>(ar, g2.x, g2.y);
        ry_real<1>(ar, g3.x, g3.y);
    }
    cnot_real<4, 8>(ar); cnot_real<2, 4>(ar); cnot_real<1, 2>(ar);

    // RZ: real -> complex via precomputed phasors
#pragma unroll
    for (int idx = 0; idx < 16; idx++) {
        float2 ph = sPh[idx];
        ai[idx] = ar[idx] * ph.y;
        ar[idx] = ar[idx] * ph.x;
    }

    // ---- layer 1 (complex; final RZ is pure phase -> skipped) ----
    {
        float2 g0 = sCS[4], g1 = sCS[5], g2 = sCS[6], g3 = sCS[7];
        ry_cplx<8>(ar, ai, g0.x, g0.y);
        ry_cplx<4>(ar, ai, g1.x, g1.y);
        ry_cplx<2>(ar, ai, g2.x, g2.y);
        ry_cplx<1>(ar, ai, g3.x, g3.y);
    }
    cnot_cplx<8, 4>(ar, ai); cnot_cplx<4, 2>(ar, ai); cnot_cplx<2, 1>(ar, ai);
    {
        float2 g0 = sCS[8], g1 = sCS[9], g2 = sCS[10], g3 = sCS[11];
        ry_cplx<8>(ar, ai, g0.x, g0.y);
        ry_cplx<4>(ar, ai, g1.x, g1.y);
        ry_cplx<2>(ar, ai, g2.x, g2.y);
        ry_cplx<1>(ar, ai, g3.x, g3.y);
    }
    cnot_cplx<4, 8>(ar, ai); cnot_cplx<2, 4>(ar, ai); cnot_cplx<1, 2>(ar, ai);

    // ---- probabilities ----
    float pv[16];
#pragma unroll
    for (int idx = 0; idx < 16; idx++)
        pv[idx] = fmaf(ar[idx], ar[idx], ai[idx] * ai[idx]);

    // ---- Z expectations via Walsh-Hadamard tree ----
    float a8[8], d8[8];
#pragma unroll
    for (int k = 0; k < 8; k++) { a8[k] = pv[2*k] + pv[2*k+1]; d8[k] = pv[2*k] - pv[2*k+1]; }
    float z3 = ((d8[0] + d8[1]) + (d8[2] + d8[3])) + ((d8[4] + d8[5]) + (d8[6] + d8[7]));
    float b4[4], e4[4];
#pragma unroll
    for (int j = 0; j < 4; j++) { b4[j] = a8[2*j] + a8[2*j+1]; e4[j] = a8[2*j] - a8[2*j+1]; }
    float z2 = (e4[0] + e4[1]) + (e4[2] + e4[3]);
    float z1 = (b4[0] - b4[1]) + (b4[2] - b4[3]);
    float z0 = (b4[0] + b4[1]) - (b4[2] + b4[3]);

    const int b_out = half * 256 + tid;
    *reinterpret_cast<float4*>(out + b_out * 784 + p * 4) = make_float4(z0, z1, z2, z3);
}

// ---------------------------------------------------------------------------
extern "C" void kernel_launch(void* const* d_in, const int* in_sizes, int n_in,
                              void* d_out, int out_size) {
    const float* x = (const float*)d_in[0];
    const float* params = (const float*)d_in[1];
    if (n_in >= 2 && in_sizes[0] == 24) {   // robustness vs input ordering
        x = (const float*)d_in[1];
        params = (const float*)d_in[0];
    }
    float* out = (float*)d_out;

    qf_fused_kernel<<<2 * NUM_P, 256>>>(x, params, out);
}